// round 3
// baseline (speedup 1.0000x reference)
#include <cuda_runtime.h>
#include <math_constants.h>

#define N_NODES 50000
#define N_EDGES 1600000
#define HEADS 8
#define OUT_FEAT 16
#define IN_FEAT 128
#define HF 128            // HEADS*OUT_FEAT

// ---- scratch (device globals; no allocations allowed) ----
__device__ float4 g_h4[N_NODES * 32];      // h as float4 [N][H][4] = 25.6 MB
__device__ float4 g_post[N_NODES * HEADS]; // (loc_l, loc_r, lsl, lsr), 6.4 MB
__device__ float  g_e[N_EDGES * HEADS];    // scores in CSR slot order, 51.2 MB
__device__ int    g_cnt[N_NODES];          // in-degree histogram
__device__ int    g_cursor[N_NODES];       // scatter cursors
__device__ int    g_off[N_NODES + 1];      // CSR offsets
__device__ int    g_slot[N_EDGES];         // edge -> CSR slot
__device__ int    g_csrc[N_EDGES];         // CSR slot -> src node

// ---- zero counters ----
__global__ void k_zero() {
    int i = blockIdx.x * blockDim.x + threadIdx.x;
    if (i < N_NODES) { g_cnt[i] = 0; g_cursor[i] = 0; }
}

// ---- in-degree histogram ----
__global__ void k_hist(const int* __restrict__ dst) {
    int e = blockIdx.x * blockDim.x + threadIdx.x;
    if (e < N_EDGES) atomicAdd(&g_cnt[dst[e]], 1);
}

// ---- exclusive prefix sum over g_cnt (single block, 1024 threads) ----
__global__ void k_scan() {
    __shared__ int s[1024];
    const int CH = (N_NODES + 1023) / 1024;   // 49
    int t = threadIdx.x;
    int base = t * CH;
    int sum = 0;
    for (int i = 0; i < CH; ++i) {
        int idx = base + i;
        if (idx < N_NODES) sum += g_cnt[idx];
    }
    s[t] = sum;
    __syncthreads();
    for (int o = 1; o < 1024; o <<= 1) {
        int v = (t >= o) ? s[t - o] : 0;
        __syncthreads();
        s[t] += v;
        __syncthreads();
    }
    int run = (t > 0) ? s[t - 1] : 0;
    for (int i = 0; i < CH; ++i) {
        int idx = base + i;
        if (idx < N_NODES) { g_off[idx] = run; run += g_cnt[idx]; }
    }
    if (t == 1023) g_off[N_NODES] = s[1023];
}

// ---- scatter: assign CSR slots ----
__global__ void k_scatter(const int* __restrict__ src, const int* __restrict__ dst) {
    int e = blockIdx.x * blockDim.x + threadIdx.x;
    if (e >= N_EDGES) return;
    int d = dst[e];
    int slot = g_off[d] + atomicAdd(&g_cursor[d], 1);
    g_slot[e] = slot;
    g_csrc[slot] = src[e];
}

// ---- projection: h = feat @ W_fc ; post = h @ W_post + b_post ----
__global__ void k_proj(const float* __restrict__ feat, const float* __restrict__ W_fc,
                       const float* __restrict__ W_post, const float* __restrict__ b_post) {
    __shared__ float sf[32][IN_FEAT];
    __shared__ float sw[32][HF];
    int t = threadIdx.x;
    int n0 = blockIdx.x * 32;

    for (int i = t; i < 32 * IN_FEAT; i += 256) {
        int r = i >> 7, c = i & 127;
        int n = n0 + r;
        sf[r][c] = (n < N_NODES) ? feat[n * IN_FEAT + c] : 0.0f;
    }

    float acc[16];
#pragma unroll
    for (int j = 0; j < 16; ++j) acc[j] = 0.0f;

    int r  = t >> 3;
    int hd = t & 7;
    int c0 = hd * 16;

    for (int kc = 0; kc < IN_FEAT; kc += 32) {
        __syncthreads();
        for (int i = t; i < 32 * HF; i += 256) {
            int kk = i >> 7, c = i & 127;
            sw[kk][c] = W_fc[(kc + kk) * HF + c];
        }
        __syncthreads();
#pragma unroll 8
        for (int kk = 0; kk < 32; ++kk) {
            float a = sf[r][kc + kk];
#pragma unroll
            for (int j = 0; j < 16; ++j) acc[j] = fmaf(a, sw[kk][c0 + j], acc[j]);
        }
    }

    int n = n0 + r;
    if (n < N_NODES) {
#pragma unroll
        for (int q = 0; q < 4; ++q)
            g_h4[n * 32 + hd * 4 + q] =
                make_float4(acc[4 * q], acc[4 * q + 1], acc[4 * q + 2], acc[4 * q + 3]);
        float p0 = b_post[0], p1 = b_post[1], p2 = b_post[2], p3 = b_post[3];
#pragma unroll
        for (int j = 0; j < 16; ++j) {
            float hv = acc[j];
            p0 = fmaf(hv, W_post[j * 4 + 0], p0);
            p1 = fmaf(hv, W_post[j * 4 + 1], p1);
            p2 = fmaf(hv, W_post[j * 4 + 2], p2);
            p3 = fmaf(hv, W_post[j * 4 + 3], p3);
        }
        g_post[n * HEADS + hd] = make_float4(p0, p1, p2, p3);
    }
}

// ---- per-edge score, written to CSR slot position ----
__global__ void k_edge(const int* __restrict__ src, const int* __restrict__ dst,
                       const float* __restrict__ eps) {
    int i = blockIdx.x * blockDim.x + threadIdx.x;
    if (i >= N_EDGES * HEADS) return;
    int e = i >> 3, hd = i & 7;
    int s = src[e], d = dst[e];
    float4 ps = g_post[s * HEADS + hd];
    float4 pd = g_post[d * HEADS + hd];
    float ev = (ps.x + pd.y) + __expf(ps.z + pd.w) * eps[i];
    g_e[g_slot[e] * HEADS + hd] = ev;
}

// ---- per-node softmax + aggregation: one warp per dst node ----
// phase 1/2: lane group (lane&7)=head, (lane>>3)=slot-subgroup; shuffles reduce.
// phase 3: lane l -> head l>>2, float4 chunk l&3; acc in registers; one store.
__global__ void k_node(const float* __restrict__ bias, float* __restrict__ out) {
    int w = (int)((blockIdx.x * (unsigned)blockDim.x + threadIdx.x) >> 5);
    int lane = threadIdx.x & 31;
    if (w >= N_NODES) return;
    int beg = g_off[w], end = g_off[w + 1];
    unsigned full = 0xFFFFFFFFu;

    // phase 1: per-head max
    float mx = -CUDART_INF_F;
    for (int s4 = beg + (lane >> 3); s4 < end; s4 += 4)
        mx = fmaxf(mx, g_e[s4 * 8 + (lane & 7)]);
    mx = fmaxf(mx, __shfl_xor_sync(full, mx, 8));
    mx = fmaxf(mx, __shfl_xor_sync(full, mx, 16));

    // phase 2: per-head denom
    float ds = 0.0f;
    for (int s4 = beg + (lane >> 3); s4 < end; s4 += 4)
        ds += __expf(g_e[s4 * 8 + (lane & 7)] - mx);
    ds += __shfl_xor_sync(full, ds, 8);
    ds += __shfl_xor_sync(full, ds, 16);

    int hd = lane >> 2;
    float m  = __shfl_sync(full, mx, hd);
    float rd = __shfl_sync(full, 1.0f / ds, hd);

    // phase 3: weighted aggregation in registers
    float4 acc = ((const float4*)bias)[lane];
    for (int s = beg; s < end; ++s) {
        int sn = g_csrc[s];
        float a = __expf(g_e[s * 8 + hd] - m) * rd;
        float4 hv = g_h4[sn * 32 + hd * 4 + (lane & 3)];
        acc.x = fmaf(hv.x, a, acc.x);
        acc.y = fmaf(hv.y, a, acc.y);
        acc.z = fmaf(hv.z, a, acc.z);
        acc.w = fmaf(hv.w, a, acc.w);
    }
    ((float4*)out)[w * 32 + lane] = acc;
}

extern "C" void kernel_launch(void* const* d_in, const int* in_sizes, int n_in,
                              void* d_out, int out_size) {
    const float* feat   = (const float*)d_in[0];
    const int*   src    = (const int*)  d_in[1];
    const int*   dst    = (const int*)  d_in[2];
    const float* eps    = (const float*)d_in[3];
    const float* W_fc   = (const float*)d_in[4];
    const float* W_post = (const float*)d_in[5];
    const float* b_post = (const float*)d_in[6];
    const float* bias   = (const float*)d_in[7];
    float* out = (float*)d_out;

    k_zero   <<<(N_NODES + 255) / 256, 256>>>();
    k_proj   <<<(N_NODES + 31) / 32, 256>>>(feat, W_fc, W_post, b_post);
    k_hist   <<<(N_EDGES + 255) / 256, 256>>>(dst);
    k_scan   <<<1, 1024>>>();
    k_scatter<<<(N_EDGES + 255) / 256, 256>>>(src, dst);
    k_edge   <<<(N_EDGES * HEADS + 255) / 256, 256>>>(src, dst, eps);
    k_node   <<<(N_NODES * 32 + 255) / 256, 256>>>(bias, out);
}

// round 4
// speedup vs baseline: 1.3898x; 1.3898x over previous
#include <cuda_runtime.h>
#include <math_constants.h>

#define N_NODES 50000
#define N_EDGES 1600000
#define HEADS 8
#define OUT_FEAT 16
#define IN_FEAT 128
#define HF 128            // HEADS*OUT_FEAT
#define CAP 128           // per-node slot capacity (max in-degree; Poisson(32) => safe)

// ---- scratch (device globals; no allocations allowed) ----
__device__ float4 g_h4[N_NODES * 32];          // h as float4 [N][H][4] = 25.6 MB
__device__ float4 g_post[N_NODES * HEADS];     // (loc_l, loc_r, lsl, lsr), 6.4 MB
__device__ float  g_e[(size_t)N_NODES * CAP * HEADS]; // scores, bucket layout, 204.8 MB (sparse-touched)
__device__ int    g_csrc[N_NODES * CAP];       // slot -> src node, 25.6 MB (sparse-touched)
__device__ int    g_cur[N_NODES];              // per-node slot cursor / final count

// ---- zero cursors ----
__global__ void k_zero() {
    int i = blockIdx.x * blockDim.x + threadIdx.x;
    if (i < N_NODES) g_cur[i] = 0;
}

// ---- projection: h = feat @ W_fc ; post = h @ W_post + b_post ----
__global__ void k_proj(const float* __restrict__ feat, const float* __restrict__ W_fc,
                       const float* __restrict__ W_post, const float* __restrict__ b_post) {
    __shared__ float sf[32][IN_FEAT];
    __shared__ float sw[32][HF];
    int t = threadIdx.x;
    int n0 = blockIdx.x * 32;

    for (int i = t; i < 32 * IN_FEAT; i += 256) {
        int r = i >> 7, c = i & 127;
        int n = n0 + r;
        sf[r][c] = (n < N_NODES) ? feat[n * IN_FEAT + c] : 0.0f;
    }

    float acc[16];
#pragma unroll
    for (int j = 0; j < 16; ++j) acc[j] = 0.0f;

    int r  = t >> 3;
    int hd = t & 7;
    int c0 = hd * 16;

    for (int kc = 0; kc < IN_FEAT; kc += 32) {
        __syncthreads();
        for (int i = t; i < 32 * HF; i += 256) {
            int kk = i >> 7, c = i & 127;
            sw[kk][c] = W_fc[(kc + kk) * HF + c];
        }
        __syncthreads();
#pragma unroll 8
        for (int kk = 0; kk < 32; ++kk) {
            float a = sf[r][kc + kk];
#pragma unroll
            for (int j = 0; j < 16; ++j) acc[j] = fmaf(a, sw[kk][c0 + j], acc[j]);
        }
    }

    int n = n0 + r;
    if (n < N_NODES) {
#pragma unroll
        for (int q = 0; q < 4; ++q)
            g_h4[n * 32 + hd * 4 + q] =
                make_float4(acc[4 * q], acc[4 * q + 1], acc[4 * q + 2], acc[4 * q + 3]);
        float p0 = b_post[0], p1 = b_post[1], p2 = b_post[2], p3 = b_post[3];
#pragma unroll
        for (int j = 0; j < 16; ++j) {
            float hv = acc[j];
            p0 = fmaf(hv, W_post[j * 4 + 0], p0);
            p1 = fmaf(hv, W_post[j * 4 + 1], p1);
            p2 = fmaf(hv, W_post[j * 4 + 2], p2);
            p3 = fmaf(hv, W_post[j * 4 + 3], p3);
        }
        g_post[n * HEADS + hd] = make_float4(p0, p1, p2, p3);
    }
}

// ---- per-edge: assign bucket slot + compute all 8 head scores ----
// one thread per edge. reads two 128B post rows (L2-resident), writes 32B
// scores + 4B csrc into the dst node's bucket.
__global__ void k_edge(const int* __restrict__ src, const int* __restrict__ dst,
                       const float* __restrict__ eps) {
    int e = blockIdx.x * blockDim.x + threadIdx.x;
    if (e >= N_EDGES) return;
    int s = src[e], d = dst[e];
    int c = atomicAdd(&g_cur[d], 1);
    size_t slot = (size_t)d * CAP + c;
    g_csrc[slot] = s;

    const float4* eps4 = (const float4*)(eps + (size_t)e * HEADS);
    float4 ep0 = eps4[0], ep1 = eps4[1];
    float ev[8];
#pragma unroll
    for (int hd = 0; hd < 8; ++hd) {
        float4 ps = g_post[s * HEADS + hd];
        float4 pd = g_post[d * HEADS + hd];
        float epv = (hd < 4) ? ((const float*)&ep0)[hd] : ((const float*)&ep1)[hd - 4];
        ev[hd] = (ps.x + pd.y) + __expf(ps.z + pd.w) * epv;
    }
    float4* eo = (float4*)(g_e + slot * HEADS);
    eo[0] = make_float4(ev[0], ev[1], ev[2], ev[3]);
    eo[1] = make_float4(ev[4], ev[5], ev[6], ev[7]);
}

// ---- per-node softmax + aggregation: one warp per dst node ----
__global__ void k_node(const float* __restrict__ bias, float* __restrict__ out) {
    int w = (int)((blockIdx.x * (unsigned)blockDim.x + threadIdx.x) >> 5);
    int lane = threadIdx.x & 31;
    if (w >= N_NODES) return;
    int cnt = g_cur[w];
    const unsigned full = 0xFFFFFFFFu;
    const float* eb = g_e + (size_t)w * CAP * HEADS;
    const int*   cb = g_csrc + (size_t)w * CAP;

    int hd = lane >> 2;               // head for aggregation layout
    float4 acc = make_float4(0.f, 0.f, 0.f, 0.f);
    float4 bv  = ((const float4*)bias)[lane];

    if (cnt > 0) {
        // phase 1: per-head max. lane&7 = head, lane>>3 = slot subgroup (stride 4)
        float mx = -CUDART_INF_F;
        for (int s4 = (lane >> 3); s4 < cnt; s4 += 4)
            mx = fmaxf(mx, eb[s4 * 8 + (lane & 7)]);
        mx = fmaxf(mx, __shfl_xor_sync(full, mx, 8));
        mx = fmaxf(mx, __shfl_xor_sync(full, mx, 16));
        float m = __shfl_sync(full, mx, hd);   // lane 'hd' holds head hd's max

        // phase 2+3 fused: unnormalized weighted sum + denom, divide at end
        float ds = 0.0f;
        int q = lane & 3;
        int s = 0;
        for (; s + 4 <= cnt; s += 4) {
            int sn0 = cb[s], sn1 = cb[s + 1], sn2 = cb[s + 2], sn3 = cb[s + 3];
            float e0 = eb[(s    ) * 8 + hd];
            float e1 = eb[(s + 1) * 8 + hd];
            float e2 = eb[(s + 2) * 8 + hd];
            float e3 = eb[(s + 3) * 8 + hd];
            float4 h0 = g_h4[sn0 * 32 + hd * 4 + q];
            float4 h1 = g_h4[sn1 * 32 + hd * 4 + q];
            float4 h2 = g_h4[sn2 * 32 + hd * 4 + q];
            float4 h3 = g_h4[sn3 * 32 + hd * 4 + q];
            float x0 = __expf(e0 - m), x1 = __expf(e1 - m);
            float x2 = __expf(e2 - m), x3 = __expf(e3 - m);
            ds += (x0 + x1) + (x2 + x3);
            acc.x = fmaf(h0.x, x0, acc.x); acc.y = fmaf(h0.y, x0, acc.y);
            acc.z = fmaf(h0.z, x0, acc.z); acc.w = fmaf(h0.w, x0, acc.w);
            acc.x = fmaf(h1.x, x1, acc.x); acc.y = fmaf(h1.y, x1, acc.y);
            acc.z = fmaf(h1.z, x1, acc.z); acc.w = fmaf(h1.w, x1, acc.w);
            acc.x = fmaf(h2.x, x2, acc.x); acc.y = fmaf(h2.y, x2, acc.y);
            acc.z = fmaf(h2.z, x2, acc.z); acc.w = fmaf(h2.w, x2, acc.w);
            acc.x = fmaf(h3.x, x3, acc.x); acc.y = fmaf(h3.y, x3, acc.y);
            acc.z = fmaf(h3.z, x3, acc.z); acc.w = fmaf(h3.w, x3, acc.w);
        }
        for (; s < cnt; ++s) {
            int sn = cb[s];
            float x = __expf(eb[s * 8 + hd] - m);
            float4 hv = g_h4[sn * 32 + hd * 4 + q];
            ds += x;
            acc.x = fmaf(hv.x, x, acc.x); acc.y = fmaf(hv.y, x, acc.y);
            acc.z = fmaf(hv.z, x, acc.z); acc.w = fmaf(hv.w, x, acc.w);
        }
        float rd = 1.0f / ds;
        acc.x *= rd; acc.y *= rd; acc.z *= rd; acc.w *= rd;
    }
    acc.x += bv.x; acc.y += bv.y; acc.z += bv.z; acc.w += bv.w;
    ((float4*)out)[w * 32 + lane] = acc;
}

extern "C" void kernel_launch(void* const* d_in, const int* in_sizes, int n_in,
                              void* d_out, int out_size) {
    const float* feat   = (const float*)d_in[0];
    const int*   src    = (const int*)  d_in[1];
    const int*   dst    = (const int*)  d_in[2];
    const float* eps    = (const float*)d_in[3];
    const float* W_fc   = (const float*)d_in[4];
    const float* W_post = (const float*)d_in[5];
    const float* b_post = (const float*)d_in[6];
    const float* bias   = (const float*)d_in[7];
    float* out = (float*)d_out;

    k_zero <<<(N_NODES + 255) / 256, 256>>>();
    k_proj <<<(N_NODES + 31) / 32, 256>>>(feat, W_fc, W_post, b_post);
    k_edge <<<(N_EDGES + 255) / 256, 256>>>(src, dst, eps);
    k_node <<<(N_NODES * 32 + 255) / 256, 256>>>(bias, out);
}

// round 5
// speedup vs baseline: 3.7642x; 2.7084x over previous
#include <cuda_runtime.h>
#include <math_constants.h>

#define N_NODES 50000
#define N_EDGES 1600000
#define HEADS 8
#define OUT_FEAT 16
#define IN_FEAT 128
#define HF 128            // HEADS*OUT_FEAT
#define CAP 128           // per-node slot capacity (Poisson(32); P(>128) ~ 1e-35)

// ---- scratch (device globals; no allocations allowed) ----
__device__ float4 g_h4[N_NODES * 32];      // h as float4 [N][H][4] = 25.6 MB
__device__ float4 g_post[N_NODES * HEADS]; // (loc_l, loc_r, lsl, lsr), 6.4 MB
__device__ int2   g_es[(size_t)N_NODES * CAP]; // bucket: {src, edge_id}, 51.2 MB (sparse-touched)
__device__ int    g_cur[N_NODES];          // per-node slot cursor

// ---- zero cursors ----
__global__ void k_zero() {
    int i = blockIdx.x * blockDim.x + threadIdx.x;
    if (i < N_NODES) g_cur[i] = 0;
}

// ---- projection: h = feat @ W_fc ; post = h @ W_post + b_post ----
// warp = head (uniform -> sw reads broadcast), lane = node (sf padded -> conflict-free)
__global__ void k_proj(const float* __restrict__ feat, const float* __restrict__ W_fc,
                       const float* __restrict__ W_post, const float* __restrict__ b_post) {
    __shared__ float sf[32][IN_FEAT + 1];   // +1 pad: lane-major reads conflict-free
    __shared__ float sw[32][HF];            // broadcast reads (uniform col per warp)
    int t = threadIdx.x;
    int lane = t & 31;
    int hd = t >> 5;                        // warp id == head
    int n0 = blockIdx.x * 32;
    int c0 = hd * 16;

    for (int i = t; i < 32 * IN_FEAT; i += 256) {
        int r = i >> 7, c = i & 127;
        int n = n0 + r;
        sf[r][c] = (n < N_NODES) ? feat[n * IN_FEAT + c] : 0.0f;
    }

    float acc[16];
#pragma unroll
    for (int j = 0; j < 16; ++j) acc[j] = 0.0f;

    for (int kc = 0; kc < IN_FEAT; kc += 32) {
        __syncthreads();
        for (int i = t; i < 32 * HF; i += 256) {
            int kk = i >> 7, c = i & 127;
            sw[kk][c] = W_fc[(kc + kk) * HF + c];
        }
        __syncthreads();
#pragma unroll 8
        for (int kk = 0; kk < 32; ++kk) {
            float a = sf[lane][kc + kk];
#pragma unroll
            for (int j = 0; j < 16; ++j) acc[j] = fmaf(a, sw[kk][c0 + j], acc[j]);
        }
    }

    int n = n0 + lane;
    if (n < N_NODES) {
#pragma unroll
        for (int q = 0; q < 4; ++q)
            g_h4[n * 32 + hd * 4 + q] =
                make_float4(acc[4 * q], acc[4 * q + 1], acc[4 * q + 2], acc[4 * q + 3]);
        float p0 = b_post[0], p1 = b_post[1], p2 = b_post[2], p3 = b_post[3];
#pragma unroll
        for (int j = 0; j < 16; ++j) {
            float hv = acc[j];
            p0 = fmaf(hv, W_post[j * 4 + 0], p0);
            p1 = fmaf(hv, W_post[j * 4 + 1], p1);
            p2 = fmaf(hv, W_post[j * 4 + 2], p2);
            p3 = fmaf(hv, W_post[j * 4 + 3], p3);
        }
        g_post[n * HEADS + hd] = make_float4(p0, p1, p2, p3);
    }
}

// ---- per-edge: slot assignment only (8B read, 8B write, 1 int atomic) ----
__global__ void k_edge(const int* __restrict__ src, const int* __restrict__ dst) {
    int e = blockIdx.x * blockDim.x + threadIdx.x;
    if (e >= N_EDGES) return;
    int d = dst[e];
    int c = atomicAdd(&g_cur[d], 1);
    if (c < CAP) g_es[(size_t)d * CAP + c] = make_int2(src[e], e);
}

// ---- per-node: recompute scores into smem, softmax + aggregate ----
// one warp per dst node. smem: scores [CAP][8] + src ids [CAP] per warp.
__global__ void k_node(const float* __restrict__ eps,
                       const float* __restrict__ bias, float* __restrict__ out) {
    __shared__ float ssc[8][CAP * 8];   // 32 KB
    __shared__ int   ssn[8][CAP];       // 4 KB
    int wlocal = threadIdx.x >> 5;
    int w = (int)((blockIdx.x * (unsigned)blockDim.x + threadIdx.x) >> 5);
    int lane = threadIdx.x & 31;
    if (w >= N_NODES) return;
    int cnt = min(g_cur[w], CAP);
    const unsigned full = 0xFFFFFFFFu;
    const int2* bkt = g_es + (size_t)w * CAP;
    float* sc = ssc[wlocal];
    int*   sn = ssn[wlocal];

    float4 bv = ((const float4*)bias)[lane];
    float4 acc = make_float4(0.f, 0.f, 0.f, 0.f);

    if (cnt > 0) {
        // ---- phase A: compute scores, track per-head max ----
        int h   = lane & 7;          // head for score phase
        int sub = lane >> 3;         // slot subgroup (stride 4)
        float4 pd = g_post[w * HEADS + h];   // dst params: fixed per lane
        float mx = -CUDART_INF_F;
        for (int s = sub; s < cnt; s += 4) {
            int2 se = bkt[s];                        // broadcast within subgroup
            float4 ps = g_post[se.x * HEADS + h];    // coalesced 128B per subgroup
            float ep  = eps[(size_t)se.y * HEADS + h]; // coalesced 32B per subgroup
            float ev = (ps.x + pd.y) + __expf(ps.z + pd.w) * ep;
            sc[s * 8 + h] = ev;
            if (h == 0) sn[s] = se.x;
            mx = fmaxf(mx, ev);
        }
        mx = fmaxf(mx, __shfl_xor_sync(full, mx, 8));
        mx = fmaxf(mx, __shfl_xor_sync(full, mx, 16));  // lane i: max for head i&7
        __syncwarp();

        // ---- phase B: fused exp + denom + weighted aggregation ----
        int hd = lane >> 2;          // head for aggregation layout
        int q  = lane & 3;           // float4 chunk
        float m = __shfl_sync(full, mx, hd);
        float ds = 0.0f;
        int s = 0;
        for (; s + 2 <= cnt; s += 2) {
            int sn0 = sn[s], sn1 = sn[s + 1];
            float x0 = __expf(sc[(s    ) * 8 + hd] - m);
            float x1 = __expf(sc[(s + 1) * 8 + hd] - m);
            float4 h0 = g_h4[sn0 * 32 + hd * 4 + q];
            float4 h1 = g_h4[sn1 * 32 + hd * 4 + q];
            ds += x0 + x1;
            acc.x = fmaf(h0.x, x0, acc.x); acc.y = fmaf(h0.y, x0, acc.y);
            acc.z = fmaf(h0.z, x0, acc.z); acc.w = fmaf(h0.w, x0, acc.w);
            acc.x = fmaf(h1.x, x1, acc.x); acc.y = fmaf(h1.y, x1, acc.y);
            acc.z = fmaf(h1.z, x1, acc.z); acc.w = fmaf(h1.w, x1, acc.w);
        }
        if (s < cnt) {
            int sn0 = sn[s];
            float x0 = __expf(sc[s * 8 + hd] - m);
            float4 h0 = g_h4[sn0 * 32 + hd * 4 + q];
            ds += x0;
            acc.x = fmaf(h0.x, x0, acc.x); acc.y = fmaf(h0.y, x0, acc.y);
            acc.z = fmaf(h0.z, x0, acc.z); acc.w = fmaf(h0.w, x0, acc.w);
        }
        float rd = 1.0f / ds;
        acc.x *= rd; acc.y *= rd; acc.z *= rd; acc.w *= rd;
    }
    acc.x += bv.x; acc.y += bv.y; acc.z += bv.z; acc.w += bv.w;
    ((float4*)out)[w * 32 + lane] = acc;
}

extern "C" void kernel_launch(void* const* d_in, const int* in_sizes, int n_in,
                              void* d_out, int out_size) {
    const float* feat   = (const float*)d_in[0];
    const int*   src    = (const int*)  d_in[1];
    const int*   dst    = (const int*)  d_in[2];
    const float* eps    = (const float*)d_in[3];
    const float* W_fc   = (const float*)d_in[4];
    const float* W_post = (const float*)d_in[5];
    const float* b_post = (const float*)d_in[6];
    const float* bias   = (const float*)d_in[7];
    float* out = (float*)d_out;

    k_zero <<<(N_NODES + 255) / 256, 256>>>();
    k_proj <<<(N_NODES + 31) / 32, 256>>>(feat, W_fc, W_post, b_post);
    k_edge <<<(N_EDGES + 255) / 256, 256>>>(src, dst);
    k_node <<<(N_NODES * 32 + 255) / 256, 256>>>(eps, bias, out);
}